// round 10
// baseline (speedup 1.0000x reference)
#include <cuda_runtime.h>
#include <math.h>

// NormalMixtureEM: B x L windows, K=4 components, 5 SEM iterations.
// R10 == R8 resubmit x2 (R8, R9 benches were container-acquisition failures;
// these are uncorrelated with source — R3's source also failed once then passed):
// R7 + __launch_bounds__(64, 16) register cap (80 -> 64 regs) to lift
// occupancy 34% -> ~50% (latency-bound: issue=67%, fma=36%).
// 64 threads/row, EPT=16, strided map (coalesced g stores), delta-softmax
// (3 ex2/elem, clamped), exp(mixw) in smem, shfl-tree reductions.

#define LW       1024
#define KC       4
#define NTHREADS 64
#define EPT      16         // elements per thread (LW / NTHREADS)
#define NWARPS   2
#define EPSF     1e-8f
#define HALF_LOG2E 0.7213475204444817f   // 0.5 * log2(e)

__device__ __forceinline__ float ex2f(float x) {
    float r; asm("ex2.approx.f32 %0, %1;" : "=f"(r) : "f"(x)); return r;
}
__device__ __forceinline__ float rcpf(float x) {
    float r; asm("rcp.approx.f32 %0, %1;" : "=f"(r) : "f"(x)); return r;
}

__global__ void __launch_bounds__(NTHREADS, 16)
em_kernel(const float* __restrict__ windows,
          const float* __restrict__ noise,
          const float* __restrict__ centers,
          const float* __restrict__ scales,
          const float* __restrict__ weights,
          const float* __restrict__ prior_p_param,
          const float* __restrict__ mixw,
          const float* __restrict__ blendp,
          float* __restrict__ out_g,   // [B, L, K]
          float* __restrict__ out_p,   // [B, K]
          float* __restrict__ out_a,   // [B, K]
          float* __restrict__ out_b)   // [B, K]
{
    __shared__ float s_wv[LW];            // exp(mixw), row-independent
    __shared__ float s_part[NWARPS][9];   // per-warp partials: Sg[3], Sx[3], Sq[3]
    __shared__ float s_stat[NWARPS][5];   // init: s1, s2, W, Wx, Wxx per warp
    __shared__ float s_dc0[3], s_dc1[3], s_dc2[3];  // coef diffs for k=1..3

    const int row  = blockIdx.x;
    const int tid  = threadIdx.x;
    const int lane = tid & 31;
    const int warp = tid >> 5;
    const float* __restrict__ xr = windows + (size_t)row * LW;

    // ---- load row (strided: l = tid + j*64), exp-weights to smem; stats ----
    float x[EPT];
    float s1 = 0.f, s2 = 0.f, W = 0.f, Wx = 0.f, Wxx = 0.f;
#pragma unroll
    for (int j = 0; j < EPT; j++) {
        const int l = tid + j * NTHREADS;
        float v = xr[l];
        x[j] = v;
        float wj = __expf(mixw[l]);
        s_wv[l] = wj;
        s1 += v; s2 = fmaf(v, v, s2);
        float gx = wj * v;
        W += wj; Wx += gx; Wxx = fmaf(gx, v, Wxx);
    }
#pragma unroll
    for (int o = 16; o; o >>= 1) {
        s1  += __shfl_down_sync(0xffffffffu, s1, o);
        s2  += __shfl_down_sync(0xffffffffu, s2, o);
        W   += __shfl_down_sync(0xffffffffu, W, o);
        Wx  += __shfl_down_sync(0xffffffffu, Wx, o);
        Wxx += __shfl_down_sync(0xffffffffu, Wxx, o);
    }
    if (lane == 0) {
        s_stat[warp][0]=s1; s_stat[warp][1]=s2; s_stat[warp][2]=W;
        s_stat[warp][3]=Wx; s_stat[warp][4]=Wxx;
    }
    __syncthreads();

    // ---- per-component state; lane k (k=0..3 of warp 0) owns component k ----
    float mean=0.f, varr=0.f, prior_p=0.f, blender=0.f, omb=0.f;
    float Wt=0.f, Wxt=0.f, Wxxt=0.f;
    if (tid < KC) {
        float S1=0.f, S2=0.f;
#pragma unroll
        for (int wn = 0; wn < NWARPS; wn++) {
            S1 += s_stat[wn][0]; S2 += s_stat[wn][1]; Wt += s_stat[wn][2];
            Wxt += s_stat[wn][3]; Wxxt += s_stat[wn][4];
        }
        mean = S1 * (1.0f / LW);
        varr = (S2 - S1 * S1 * (1.0f / LW)) * (1.0f / (LW - 1));   // ddof=1
        float sd = sqrtf(varr);

        float ak = centers[tid] * sd + mean + noise[row * KC + tid] * sd * 0.01f;
        float bk = fabsf(scales[tid]) * sd;
        float pk = weights[tid];
        prior_p = 1.0f / (1.0f + __expf(-prior_p_param[0]));
        blender = 1.0f / (1.0f + __expf(-blendp[0]));
        omb = 1.0f - blender;

        float binv = rcpf(bk + EPSF);
        float h = HALF_LOG2E * binv * binv;
        float c2 = -h;
        float c1 = 2.0f * h * ak;
        float c0 = __log2f((pk + EPSF) * binv) - h * ak * ak;
        float c00 = __shfl_sync(0x0000000fu, c0, 0);
        float c10 = __shfl_sync(0x0000000fu, c1, 0);
        float c20 = __shfl_sync(0x0000000fu, c2, 0);
        if (tid >= 1) {
            s_dc0[tid - 1] = c0 - c00;
            s_dc1[tid - 1] = c1 - c10;
            s_dc2[tid - 1] = c2 - c20;
        }
    }
    __syncthreads();

    float4* __restrict__ g4row = (float4*)out_g + (size_t)row * LW;

#pragma unroll
    for (int it = 0; it < 5; it++) {
        const bool last = (it == 4);
        const float d01=s_dc0[0], d02=s_dc0[1], d03=s_dc0[2];
        const float d11=s_dc1[0], d12=s_dc1[1], d13=s_dc1[2];
        const float d21=s_dc2[0], d22=s_dc2[1], d23=s_dc2[2];

        float Sg0=0.f,Sg1=0.f,Sg2=0.f, Sx0=0.f,Sx1=0.f,Sx2=0.f, Sq0=0.f,Sq1=0.f,Sq2=0.f;

#pragma unroll
        for (int j = 0; j < EPT; j++) {
            const float xv = x[j];
            // dlm_k = lm_k - lm_0 as quadratic in x (k = 1..3), clamped
            float e1 = ex2f(fminf(fmaf(fmaf(d21, xv, d11), xv, d01), 80.f));
            float e2 = ex2f(fminf(fmaf(fmaf(d22, xv, d12), xv, d02), 80.f));
            float e3 = ex2f(fminf(fmaf(fmaf(d23, xv, d13), xv, d03), 80.f));
            float rinv = rcpf(1.0f + e1 + (e2 + e3));
            if (last) {
                g4row[tid + j * NTHREADS] =
                    make_float4(rinv, e1 * rinv, e2 * rinv, e3 * rinv);
            }
            float rw = rinv * s_wv[tid + j * NTHREADS];
            float xx = xv * xv;
            float g1 = e1 * rw, g2 = e2 * rw;
            Sg0 += rw; Sx0 = fmaf(rw, xv, Sx0); Sq0 = fmaf(rw, xx, Sq0);
            Sg1 += g1; Sx1 = fmaf(g1, xv, Sx1); Sq1 = fmaf(g1, xx, Sq1);
            Sg2 += g2; Sx2 = fmaf(g2, xv, Sx2); Sq2 = fmaf(g2, xx, Sq2);
        }

        // warp shfl-tree reduce 9 accumulators
#pragma unroll
        for (int o = 16; o; o >>= 1) {
            Sg0 += __shfl_down_sync(0xffffffffu, Sg0, o);
            Sg1 += __shfl_down_sync(0xffffffffu, Sg1, o);
            Sg2 += __shfl_down_sync(0xffffffffu, Sg2, o);
            Sx0 += __shfl_down_sync(0xffffffffu, Sx0, o);
            Sx1 += __shfl_down_sync(0xffffffffu, Sx1, o);
            Sx2 += __shfl_down_sync(0xffffffffu, Sx2, o);
            Sq0 += __shfl_down_sync(0xffffffffu, Sq0, o);
            Sq1 += __shfl_down_sync(0xffffffffu, Sq1, o);
            Sq2 += __shfl_down_sync(0xffffffffu, Sq2, o);
        }
        if (lane == 0) {
            s_part[warp][0]=Sg0; s_part[warp][1]=Sg1; s_part[warp][2]=Sg2;
            s_part[warp][3]=Sx0; s_part[warp][4]=Sx1; s_part[warp][5]=Sx2;
            s_part[warp][6]=Sq0; s_part[warp][7]=Sq1; s_part[warp][8]=Sq2;
        }
        __syncthreads();

        // m-step: lane k handles component k; comp3 sums from row totals
        if (tid < KC) {
            float rg = 0.f, rx = 0.f, rq = 0.f;
            if (tid < 3) {
#pragma unroll
                for (int wn = 0; wn < NWARPS; wn++) {
                    rg += s_part[wn][tid];
                    rx += s_part[wn][3 + tid];
                    rq += s_part[wn][6 + tid];
                }
            }
            // totals over lanes 0-3 (lane 3 contributes 0)
            float tg = rg + __shfl_xor_sync(0x0000000fu, rg, 1);
            tg += __shfl_xor_sync(0x0000000fu, tg, 2);
            float tx = rx + __shfl_xor_sync(0x0000000fu, rx, 1);
            tx += __shfl_xor_sync(0x0000000fu, tx, 2);
            float tq = rq + __shfl_xor_sync(0x0000000fu, rq, 1);
            tq += __shfl_xor_sync(0x0000000fu, tq, 2);
            if (tid == 3) { rg = Wt - tg; rx = Wxt - tx; rq = Wxxt - tq; }

            float sg = fmaxf(rg, EPSF);
            float pt = sg + prior_p;
            float t2 = pt + __shfl_xor_sync(0x0000000fu, pt, 1);
            float psum = t2 + __shfl_xor_sync(0x0000000fu, t2, 2);
            float pk = pt * rcpf(psum);
            float sginv = rcpf(sg);
            float da = rx * sginv;
            float ak = da * blender + mean * omb;                      // prior_a = mean
            float dv = fmaf(ak, fmaf(ak, rg, -2.0f * rx), rq) * sginv; // Sq-2aSx+a^2Sg
            float bk = sqrtf(dv * blender + varr * omb + EPSF);

            float binv = rcpf(bk + EPSF);
            float h = HALF_LOG2E * binv * binv;
            float c2 = -h;
            float c1 = 2.0f * h * ak;
            float c0 = __log2f((pk + EPSF) * binv) - h * ak * ak;
            float c00 = __shfl_sync(0x0000000fu, c0, 0);
            float c10 = __shfl_sync(0x0000000fu, c1, 0);
            float c20 = __shfl_sync(0x0000000fu, c2, 0);
            if (tid >= 1) {
                s_dc0[tid - 1] = c0 - c00;
                s_dc1[tid - 1] = c1 - c10;
                s_dc2[tid - 1] = c2 - c20;
            }

            if (last) {
                out_p[row * KC + tid] = pk;
                out_a[row * KC + tid] = ak;
                out_b[row * KC + tid] = bk;
            }
        }
        __syncthreads();
    }
}

extern "C" void kernel_launch(void* const* d_in, const int* in_sizes, int n_in,
                              void* d_out, int out_size)
{
    const float* windows  = (const float*)d_in[0];  // [B, L]
    const float* noise    = (const float*)d_in[1];  // [B, K]
    const float* centers  = (const float*)d_in[2];  // [K]
    const float* scales   = (const float*)d_in[3];  // [K]
    const float* weights  = (const float*)d_in[4];  // [K]
    const float* prior_pp = (const float*)d_in[5];  // [1]
    const float* mixw     = (const float*)d_in[6];  // [1, L]
    const float* blend    = (const float*)d_in[7];  // [1]

    const int Brows = in_sizes[0] / LW;

    float* out = (float*)d_out;
    float* out_g = out;                                 // [B,L,K]
    float* out_p = out + (size_t)Brows * LW * KC;       // [B,K]
    float* out_a = out_p + (size_t)Brows * KC;
    float* out_b = out_a + (size_t)Brows * KC;

    em_kernel<<<Brows, NTHREADS>>>(windows, noise, centers, scales, weights,
                                   prior_pp, mixw, blend,
                                   out_g, out_p, out_a, out_b);
}